// round 8
// baseline (speedup 1.0000x reference)
#include <cuda_runtime.h>
#include <cuda_bf16.h>
#include <cstdint>

// ============================================================================
// HyperGRUCell — round 8: register-diet Gram hyp_fused (VPT=2, 512 thr, <=64 regs)
//   split_act : fp32 -> bf16 hi/lo for [inp; prev_h]           (K-major)
//   split_wt  : fp32 W[k][n] -> bf16 hi/lo Wt[n][k] (transpose, K-major)
//   gemm6     : C = Ahi@Whi^T + Ahi@Wlo^T + Alo@Whi^T  (fp32 accum, HMMA)
//   hyp_fused : 2 fused reduction passes via Gram-matrix algebra
// ============================================================================

#define MDIM 4096
#define NDIM 1024
#define KDIM 1024
#define GSZ  ((size_t)MDIM * NDIM)

__device__ float         g_C[6ull * MDIM * NDIM];
__device__ __nv_bfloat16 g_Ahi[8192ull * 1024];
__device__ __nv_bfloat16 g_Alo[8192ull * 1024];
__device__ __nv_bfloat16 g_Whi[6144ull * 1024];
__device__ __nv_bfloat16 g_Wlo[6144ull * 1024];

// ----------------------------------------------------------------------------
// split kernels (unchanged)
// ----------------------------------------------------------------------------
__global__ void __launch_bounds__(256) split_act(const float* __restrict__ inp,
                                                 const float* __restrict__ prevh)
{
    const size_t i = ((size_t)blockIdx.x * 256 + threadIdx.x) * 4;
    const size_t half = (size_t)MDIM * KDIM;
    const float* src = (i < half) ? (inp + i) : (prevh + (i - half));
    float4 v = *reinterpret_cast<const float4*>(src);
    float x[4] = {v.x, v.y, v.z, v.w};
    uint32_t hp[2], lp[2];
#pragma unroll
    for (int j = 0; j < 2; j++) {
        __nv_bfloat16 h0 = __float2bfloat16_rn(x[2 * j]);
        __nv_bfloat16 h1 = __float2bfloat16_rn(x[2 * j + 1]);
        __nv_bfloat16 l0 = __float2bfloat16_rn(x[2 * j] - __bfloat162float(h0));
        __nv_bfloat16 l1 = __float2bfloat16_rn(x[2 * j + 1] - __bfloat162float(h1));
        hp[j] = (uint32_t)__bfloat16_as_ushort(h0) |
                ((uint32_t)__bfloat16_as_ushort(h1) << 16);
        lp[j] = (uint32_t)__bfloat16_as_ushort(l0) |
                ((uint32_t)__bfloat16_as_ushort(l1) << 16);
    }
    *reinterpret_cast<uint2*>(reinterpret_cast<char*>(g_Ahi) + i * 2) = make_uint2(hp[0], hp[1]);
    *reinterpret_cast<uint2*>(reinterpret_cast<char*>(g_Alo) + i * 2) = make_uint2(lp[0], lp[1]);
}

struct WPtrs { const float* w[6]; };

__global__ void __launch_bounds__(256) split_wt(WPtrs wp)
{
    __shared__ float t[32][33];
    const int g = blockIdx.z;
    const float* __restrict__ W = wp.w[g];
    const int tx = threadIdx.x & 31, ty = threadIdx.x >> 5;
    const int n0 = blockIdx.x * 32, k0 = blockIdx.y * 32;
#pragma unroll
    for (int j = 0; j < 4; j++)
        t[ty + j * 8][tx] = W[(size_t)(k0 + ty + j * 8) * NDIM + n0 + tx];
    __syncthreads();
#pragma unroll
    for (int j = 0; j < 4; j++) {
        const float v = t[tx][ty + j * 8];
        __nv_bfloat16 h = __float2bfloat16_rn(v);
        __nv_bfloat16 l = __float2bfloat16_rn(v - __bfloat162float(h));
        const size_t o = (size_t)(g * 1024 + n0 + ty + j * 8) * KDIM + k0 + tx;
        g_Whi[o] = h;
        g_Wlo[o] = l;
    }
}

// ----------------------------------------------------------------------------
// gemm6 (unchanged — at legacy HMMA rate floor)
// ----------------------------------------------------------------------------
#define SSTRIDE 40
#define MAT_ELEMS (128 * SSTRIDE)
#define STAGE_ELEMS (4 * MAT_ELEMS)
#define NSTAGE 2
#define SMEM_BYTES (NSTAGE * STAGE_ELEMS * 2)

__device__ __forceinline__ void cp16(uint32_t dst, const void* src)
{
    asm volatile("cp.async.cg.shared.global [%0], [%1], 16;"
                 :: "r"(dst), "l"(src) : "memory");
}
#define CP_COMMIT() asm volatile("cp.async.commit_group;" ::: "memory")
#define CP_WAIT(n)  asm volatile("cp.async.wait_group %0;" :: "n"(n) : "memory")

__device__ __forceinline__ void ldsm4(uint32_t* d, uint32_t addr)
{
    asm volatile("ldmatrix.sync.aligned.m8n8.x4.shared.b16 {%0,%1,%2,%3}, [%4];"
                 : "=r"(d[0]), "=r"(d[1]), "=r"(d[2]), "=r"(d[3]) : "r"(addr));
}

__device__ __forceinline__ void mma16816(float* c, const uint32_t* a,
                                         const uint32_t* b)
{
    asm volatile(
        "mma.sync.aligned.m16n8k16.row.col.f32.bf16.bf16.f32 "
        "{%0,%1,%2,%3}, {%4,%5,%6,%7}, {%8,%9}, {%0,%1,%2,%3};"
        : "+f"(c[0]), "+f"(c[1]), "+f"(c[2]), "+f"(c[3])
        : "r"(a[0]), "r"(a[1]), "r"(a[2]), "r"(a[3]), "r"(b[0]), "r"(b[1]));
}

__global__ void __launch_bounds__(256, 2) gemm6()
{
    extern __shared__ __nv_bfloat16 smem[];
    uint32_t sb;
    asm("{ .reg .u64 t; cvta.to.shared.u64 t, %1; cvt.u32.u64 %0, t; }"
        : "=r"(sb) : "l"(smem));

    const int tid  = threadIdx.x;
    const int lane = tid & 31, wid = tid >> 5;
    const int wm = wid >> 2, wn = wid & 3;

    const int g  = blockIdx.z;
    const int bm = blockIdx.y * 128;
    const int bn = blockIdx.x * 128;
    const int arow = ((g & 1) << 12) + bm;
    const int wrow = (g << 10) + bn;

    const __nv_bfloat16* gb[4] = {
        g_Ahi + (size_t)arow * KDIM, g_Alo + (size_t)arow * KDIM,
        g_Whi + (size_t)wrow * KDIM, g_Wlo + (size_t)wrow * KDIM};

    int l_mat[8], l_row[8], l_ch[8];
#pragma unroll
    for (int i = 0; i < 8; i++) {
        const int idx = tid + i * 256;
        l_mat[i] = idx >> 9;
        const int wi = idx & 511;
        l_row[i] = wi >> 2;
        l_ch[i]  = wi & 3;
    }

#define LOAD_STAGE(kt, s)                                                      \
    do {                                                                       \
        const uint32_t sbase_ = sb + (uint32_t)(s) * (STAGE_ELEMS * 2);        \
        _Pragma("unroll")                                                      \
        for (int i = 0; i < 8; i++) {                                          \
            const uint32_t dst = sbase_ +                                      \
                (uint32_t)(l_mat[i] * MAT_ELEMS + l_row[i] * SSTRIDE +         \
                           l_ch[i] * 8) * 2;                                   \
            cp16(dst, gb[l_mat[i]] + (size_t)l_row[i] * KDIM +                 \
                      (kt) * 32 + l_ch[i] * 8);                                \
        }                                                                      \
    } while (0)

    float acc[4][4][4];
#pragma unroll
    for (int mt = 0; mt < 4; mt++)
#pragma unroll
        for (int nt = 0; nt < 4; nt++)
#pragma unroll
            for (int j = 0; j < 4; j++) acc[mt][nt][j] = 0.f;

    LOAD_STAGE(0, 0); CP_COMMIT();
    LOAD_STAGE(1, 1); CP_COMMIT();

    const int a_r = (lane & 7) + ((lane >> 3) & 1) * 8;
    const int a_c = (lane >> 4) * 8;
    const int b_r = (lane & 7) + (lane >> 4) * 8;
    const int b_c = ((lane >> 3) & 1) * 8;

    for (int kt = 0; kt < 32; kt++) {
        CP_WAIT(1);
        __syncthreads();

        const uint32_t sbase = sb + (uint32_t)(kt & 1) * (STAGE_ELEMS * 2);
#pragma unroll
        for (int ks = 0; ks < 2; ks++) {
            uint32_t a[4][4], bq[4][2], tb[4][2];
#pragma unroll
            for (int mt = 0; mt < 4; mt++)
                ldsm4(a[mt], sbase +
                      (uint32_t)((wm * 64 + mt * 16 + a_r) * SSTRIDE +
                                 ks * 16 + a_c) * 2);
#pragma unroll
            for (int p = 0; p < 2; p++) {
                uint32_t q[4];
                ldsm4(q, sbase + (uint32_t)(2 * MAT_ELEMS +
                        (wn * 32 + p * 16 + b_r) * SSTRIDE + ks * 16 + b_c) * 2);
                bq[2 * p][0] = q[0]; bq[2 * p][1] = q[1];
                bq[2 * p + 1][0] = q[2]; bq[2 * p + 1][1] = q[3];
            }
#pragma unroll
            for (int mt = 0; mt < 4; mt++)
#pragma unroll
                for (int nt = 0; nt < 4; nt++)
                    mma16816(acc[mt][nt], a[mt], bq[nt]);
#pragma unroll
            for (int p = 0; p < 2; p++) {
                uint32_t q[4];
                ldsm4(q, sbase + (uint32_t)(3 * MAT_ELEMS +
                        (wn * 32 + p * 16 + b_r) * SSTRIDE + ks * 16 + b_c) * 2);
                tb[2 * p][0] = q[0]; tb[2 * p][1] = q[1];
                tb[2 * p + 1][0] = q[2]; tb[2 * p + 1][1] = q[3];
            }
#pragma unroll
            for (int mt = 0; mt < 4; mt++)
#pragma unroll
                for (int nt = 0; nt < 4; nt++)
                    mma16816(acc[mt][nt], a[mt], tb[nt]);
#pragma unroll
            for (int mt = 0; mt < 4; mt++)
                ldsm4(a[mt], sbase +
                      (uint32_t)(MAT_ELEMS +
                                 (wm * 64 + mt * 16 + a_r) * SSTRIDE +
                                 ks * 16 + a_c) * 2);
#pragma unroll
            for (int mt = 0; mt < 4; mt++)
#pragma unroll
                for (int nt = 0; nt < 4; nt++)
                    mma16816(acc[mt][nt], a[mt], bq[nt]);
        }

        __syncthreads();
        if (kt + 2 < 32) LOAD_STAGE(kt + 2, kt & 1);
        CP_COMMIT();
    }
    CP_WAIT(0);

    float* Cb = g_C + (size_t)g * GSZ;
    const int mrow = bm + wm * 64 + (lane >> 2);
    const int ncol = bn + wn * 32 + (lane & 3) * 2;
#pragma unroll
    for (int mt = 0; mt < 4; mt++) {
#pragma unroll
        for (int nt = 0; nt < 4; nt++) {
            float* p0 = Cb + (size_t)(mrow + mt * 16) * NDIM + ncol + nt * 8;
            *reinterpret_cast<float2*>(p0) =
                make_float2(acc[mt][nt][0], acc[mt][nt][1]);
            *reinterpret_cast<float2*>(p0 + 8 * NDIM) =
                make_float2(acc[mt][nt][2], acc[mt][nt][3]);
        }
    }
#undef LOAD_STAGE
}

// ----------------------------------------------------------------------------
// hyp_fused — 2-pass Gram, VPT=2 / 512 threads / <=64 regs
// ----------------------------------------------------------------------------
#define RT 512
#define VPT 2
#define NWARP 16

__device__ __forceinline__ float artanh_c(float x)
{
    x = fminf(fmaxf(x, -1.f + 1e-5f), 1.f - 1e-5f);
    return 0.5f * __logf(__fdividef(1.f + x, 1.f - x));
}

__device__ __forceinline__ float tanh_pos(float v)   // v >= 0
{
    return 1.f - __fdividef(2.f, __expf(2.f * v) + 1.f);
}

__device__ __forceinline__ float sigmoid_f(float v)
{
    return __fdividef(1.f, 1.f + __expf(-v));
}

__device__ __forceinline__ void safe_norm(float v2, float& inv_n, float& n)
{
    const float vc = fmaxf(v2, 1e-15f);
    inv_n = rsqrtf(vc);
    n = vc * inv_n;
}

__device__ __forceinline__ float mv_factor(float g2, float inv_xn, float atx)
{
    float inv_gn, gn;
    safe_norm(g2, inv_gn, gn);
    return tanh_pos(gn * inv_xn * atx) * inv_gn;
}

__device__ __forceinline__ void madd_coef(float ab, float a2, float b2,
                                          float& cA, float& cB)
{
    const float inv = __fdividef(1.f, 1.f + 2.f * ab + a2 * b2);
    cA = (1.f + 2.f * ab + b2) * inv;
    cB = (1.f - a2) * inv;
}

template <int N>
__device__ __forceinline__ void blockReduceN(float* v, float* buf)
{
    const int lane = threadIdx.x & 31, wid = threadIdx.x >> 5;
#pragma unroll
    for (int o = 16; o; o >>= 1)
#pragma unroll
        for (int i = 0; i < N; i++)
            v[i] += __shfl_xor_sync(0xffffffffu, v[i], o);
    if (lane == 0)
#pragma unroll
        for (int i = 0; i < N; i++) buf[wid * N + i] = v[i];
    __syncthreads();
#pragma unroll
    for (int i = 0; i < N; i++) {
        float s = 0.f;
#pragma unroll
        for (int w = 0; w < NWARP; w++) s += buf[w * N + i];
        v[i] = s;
    }
}

__global__ void __launch_bounds__(512, 2) hyp_fused(
    const float* __restrict__ inp, const float* __restrict__ prevh,
    const float* __restrict__ bzp, const float* __restrict__ brp,
    const float* __restrict__ bhp, float* __restrict__ out)
{
    __shared__ float buf1[NWARP * 19];
    const int tid = threadIdx.x;
    const size_t off = (size_t)blockIdx.x * NDIM;

    // ---- pass-1 loads + Gram partial sums (biases as temporaries) ----
    float H[VPT], G0[VPT], G1[VPT], G2[VPT], G3[VPT], G4[VPT], G5[VPT];
    float s[19];
#pragma unroll
    for (int i = 0; i < 19; i++) s[i] = 0.f;

#pragma unroll
    for (int j = 0; j < VPT; j++) {
        const int c = j * RT + tid;
        const float xv = inp[off + c];
        H[j]  = prevh[off + c];
        G0[j] = g_C[0 * GSZ + off + c];
        G1[j] = g_C[1 * GSZ + off + c];
        G2[j] = g_C[2 * GSZ + off + c];
        G3[j] = g_C[3 * GSZ + off + c];
        G4[j] = g_C[4 * GSZ + off + c];
        G5[j] = g_C[5 * GSZ + off + c];
        const float bz = bzp[c];
        const float br = brp[c];
        const float bh = bhp[c];
        s[0]  = fmaf(xv, xv, s[0]);            // xx
        s[1]  = fmaf(H[j], H[j], s[1]);        // hh
        s[2]  = fmaf(G0[j], G0[j], s[2]);      // g00
        s[3]  = fmaf(G1[j], G1[j], s[3]);      // g11
        s[4]  = fmaf(G0[j], G1[j], s[4]);      // g01
        s[5]  = fmaf(G0[j], bz, s[5]);         // g0z
        s[6]  = fmaf(G1[j], bz, s[6]);         // g1z
        s[7]  = fmaf(bz, bz, s[7]);            // zz
        s[8]  = fmaf(G2[j], G2[j], s[8]);      // g22
        s[9]  = fmaf(G3[j], G3[j], s[9]);      // g33
        s[10] = fmaf(G2[j], G3[j], s[10]);     // g23
        s[11] = fmaf(G2[j], br, s[11]);        // g2r
        s[12] = fmaf(G3[j], br, s[12]);        // g3r
        s[13] = fmaf(br, br, s[13]);           // rrb
        s[14] = fmaf(G5[j], G5[j], s[14]);     // g55
        s[15] = fmaf(G5[j], bh, s[15]);        // g5h
        s[16] = fmaf(bh, bh, s[16]);           // bhbh
        s[17] = fmaf(G4[j], G4[j], s[17]);     // g44
        s[18] = fmaf(G4[j], H[j], s[18]);      // g4H
    }
    blockReduceN<19>(s, buf1);
    const float xx = s[0], hh = s[1];
    const float g00 = s[2], g11 = s[3], g01 = s[4], g0z = s[5], g1z = s[6], zz = s[7];
    const float g22 = s[8], g33 = s[9], g23 = s[10], g2r = s[11], g3r = s[12], rrb = s[13];
    const float g55 = s[14], g5h = s[15], bhbh = s[16], g44 = s[17], g4H = s[18];

    // ---- pass-1 scalar algebra ----
    float inv_xn, xn, inv_hn, hn;
    safe_norm(xx, inv_xn, xn);
    safe_norm(hh, inv_hn, hn);
    const float atx = artanh_c(xn);
    const float ath = artanh_c(hn);

    const float t0 = mv_factor(g00, inv_xn, atx);
    const float t1 = mv_factor(g11, inv_hn, ath);
    const float t2 = mv_factor(g22, inv_xn, atx);
    const float t3 = mv_factor(g33, inv_hn, ath);
    const float t4 = mv_factor(g44, inv_xn, atx);
    const float t5 = mv_factor(g55, inv_hn, ath);

    // z gate
    float cA, cB;
    madd_coef(t1 * g1z, t1 * t1 * g11, zz, cA, cB);
    const float u1 = cA * t1, u2 = cB;
    madd_coef(t0 * (u1 * g01 + u2 * g0z), t0 * t0 * g00,
              u1 * u1 * g11 + 2.f * u1 * u2 * g1z + u2 * u2 * zz, cA, cB);
    const float w0 = cA * t0, w1 = cB * u1, w2 = cB * u2;
    {
        const float nz2 = w0 * w0 * g00 + w1 * w1 * g11 + w2 * w2 * zz +
                          2.f * (w0 * w1 * g01 + w0 * w2 * g0z + w1 * w2 * g1z);
        float inv_nz, nz;
        safe_norm(nz2, inv_nz, nz);
        const float fz = artanh_c(nz) * inv_nz;
#pragma unroll
        for (int j = 0; j < VPT; j++)
            G0[j] = sigmoid_f(fz * (w0 * G0[j] + w1 * G1[j] +
                                    w2 * bzp[j * RT + tid]));
        // G0 now holds z_vec
    }

    // r gate
    madd_coef(t3 * g3r, t3 * t3 * g33, rrb, cA, cB);
    const float v1 = cA * t3, v2 = cB;
    madd_coef(t2 * (v1 * g23 + v2 * g2r), t2 * t2 * g22,
              v1 * v1 * g33 + 2.f * v1 * v2 * g3r + v2 * v2 * rrb, cA, cB);
    const float y0 = cA * t2, y1 = cB * v1, y2 = cB * v2;
    {
        const float nr2 = y0 * y0 * g22 + y1 * y1 * g33 + y2 * y2 * rrb +
                          2.f * (y0 * y1 * g23 + y0 * y2 * g2r + y1 * y2 * g3r);
        float inv_nr, nr;
        safe_norm(nr2, inv_nr, nr);
        const float fr = artanh_c(nr) * inv_nr;
#pragma unroll
        for (int j = 0; j < VPT; j++)
            G1[j] = sigmoid_f(fr * (y0 * G2[j] + y1 * G3[j] +
                                    y2 * brp[j * RT + tid]));
        // G1 now holds r_vec
    }

    // ahh = d5*G5 + db*BH
    madd_coef(t5 * g5h, t5 * t5 * g55, bhbh, cA, cB);
    const float d5 = cA * t5, db = cB;
    const float ahh2 = d5 * d5 * g55 + 2.f * d5 * db * g5h + db * db * bhbh;

    // ---- pass-2 elementwise prep + partial sums ----
    float q[VPT];
    float s2[12];
#pragma unroll
    for (int i = 0; i < 12; i++) s2[i] = 0.f;
#pragma unroll
    for (int j = 0; j < VPT; j++) {
        q[j] = G1[j] * fmaf(d5, G5[j], db * bhp[j * RT + tid]);
        const float z = G0[j];
        const float zh = z * H[j], zq = z * q[j], zg = z * G4[j];
        s2[0]  = fmaf(q[j], q[j], s2[0]);     // qq
        s2[1]  = fmaf(q[j], G4[j], s2[1]);    // qg4
        s2[2]  = fmaf(q[j], H[j], s2[2]);     // qh
        s2[3]  = fmaf(zh, zh, s2[3]);         // s11
        s2[4]  = fmaf(zh, zq, s2[4]);         // s12
        s2[5]  = fmaf(zh, zg, s2[5]);         // s13
        s2[6]  = fmaf(zq, zq, s2[6]);         // s22
        s2[7]  = fmaf(zq, zg, s2[7]);         // s23
        s2[8]  = fmaf(zg, zg, s2[8]);         // s33
        s2[9]  = fmaf(H[j], zh, s2[9]);       // hzh
        s2[10] = fmaf(H[j], zq, s2[10]);      // hzq
        s2[11] = fmaf(H[j], zg, s2[11]);      // hzg4
    }
    __syncthreads();    // buf1 reuse safety
    blockReduceN<12>(s2, buf1);
    const float qq = s2[0], qg4 = s2[1], qh = s2[2];
    const float s11 = s2[3], s12 = s2[4], s13 = s2[5];
    const float s22 = s2[6], s23 = s2[7], s33 = s2[8];
    const float hzh = s2[9], hzq = s2[10], hzg4 = s2[11];

    // ---- pass-2 scalar algebra ----
    float inv_na, na, inv_nq, nq;
    safe_norm(ahh2, inv_na, na);
    safe_norm(qq, inv_nq, nq);
    const float tp = tanh_pos(nq * inv_na * artanh_c(na)) * inv_nq;

    madd_coef(tp * t4 * qg4, tp * tp * qq, t4 * t4 * g44, cA, cB);
    const float bq = cA * tp, b4 = cB * t4;

    const float temp2 = bq * bq * qq + 2.f * bq * b4 * qg4 + b4 * b4 * g44;
    madd_coef(-(bq * qh + b4 * g4H), hh, temp2, cA, cB);
    const float alpha = -cA, bq2 = cB * bq, b42 = cB * b4;

    const float mh2 = alpha * alpha * hh + bq2 * bq2 * qq + b42 * b42 * g44 +
                      2.f * (alpha * bq2 * qh + alpha * b42 * g4H + bq2 * b42 * qg4);
    const float ux2 = alpha * alpha * s11 + bq2 * bq2 * s22 + b42 * b42 * s33 +
                      2.f * (alpha * bq2 * s12 + alpha * b42 * s13 + bq2 * b42 * s23);
    float inv_nmh, nmh, inv_nux, nux;
    safe_norm(mh2, inv_nmh, nmh);
    safe_norm(ux2, inv_nux, nux);
    const float tz = tanh_pos(nux * inv_nmh * artanh_c(nmh)) * inv_nux;

    madd_coef(tz * (alpha * hzh + bq2 * hzq + b42 * hzg4), hh, tz * tz * ux2,
              cA, cB);
    const float k0 = cA;
    const float kz = cB * tz;
    const float ka = kz * alpha, kb = kz * bq2, kc = kz * b42;

#pragma unroll
    for (int j = 0; j < VPT; j++) {
        const float z = G0[j];
        out[off + j * RT + tid] =
            k0 * H[j] + z * (ka * H[j] + kb * q[j] + kc * G4[j]);
    }
}

// ----------------------------------------------------------------------------
// launch
// ----------------------------------------------------------------------------
extern "C" void kernel_launch(void* const* d_in, const int* in_sizes, int n_in,
                              void* d_out, int out_size)
{
    const float* inp   = (const float*)d_in[0];
    const float* prevh = (const float*)d_in[1];
    WPtrs wp;
    wp.w[0] = (const float*)d_in[2];  // w_inp_z
    wp.w[1] = (const float*)d_in[3];  // w_hid_z
    wp.w[2] = (const float*)d_in[5];  // w_inp_r
    wp.w[3] = (const float*)d_in[6];  // w_hid_r
    wp.w[4] = (const float*)d_in[8];  // w_inp_h
    wp.w[5] = (const float*)d_in[9];  // w_hid_h
    const float* b_z = (const float*)d_in[4];
    const float* b_r = (const float*)d_in[7];
    const float* b_h = (const float*)d_in[10];
    float* out = (float*)d_out;

    cudaFuncSetAttribute(gemm6, cudaFuncAttributeMaxDynamicSharedMemorySize,
                         SMEM_BYTES);

    split_act<<<8192, 256>>>(inp, prevh);
    split_wt<<<dim3(32, 32, 6), 256>>>(wp);
    gemm6<<<dim3(8, 32, 6), 256, SMEM_BYTES>>>();
    hyp_fused<<<MDIM, 512>>>(inp, prevh, b_z, b_r, b_h, out);
}

// round 9
// speedup vs baseline: 1.5492x; 1.5492x over previous
#include <cuda_runtime.h>
#include <cuda_bf16.h>
#include <cuda_fp16.h>
#include <cstdint>

// ============================================================================
// HyperGRUCell — round 9: fp16 2-product HMMA GEMM + round-7 Gram hyp_fused
//   split_act : fp32 -> fp16 hi/lo for [inp; prev_h]           (K-major)
//   split_wt  : fp32 W[k][n] -> fp16 Wt[n][k] (transpose, K-major, 1 copy)
//   gemm6     : C = Ahi@W^T + Alo@W^T   (fp32 accum, HMMA, 2 products)
//   hyp_fused : 2-pass Gram (round-7 proven: VPT=4/256thr, 72.4us)
// ============================================================================

#define MDIM 4096
#define NDIM 1024
#define KDIM 1024
#define GSZ  ((size_t)MDIM * NDIM)

__device__ float  g_C[6ull * MDIM * NDIM];
__device__ __half g_Ah[8192ull * 1024];
__device__ __half g_Al[8192ull * 1024];
__device__ __half g_Wh[6144ull * 1024];

// ----------------------------------------------------------------------------
// split kernels
// ----------------------------------------------------------------------------
__global__ void __launch_bounds__(256) split_act(const float* __restrict__ inp,
                                                 const float* __restrict__ prevh)
{
    const size_t i = ((size_t)blockIdx.x * 256 + threadIdx.x) * 4;
    const size_t half = (size_t)MDIM * KDIM;
    const float* src = (i < half) ? (inp + i) : (prevh + (i - half));
    float4 v = *reinterpret_cast<const float4*>(src);
    float x[4] = {v.x, v.y, v.z, v.w};
    uint32_t hp[2], lp[2];
#pragma unroll
    for (int j = 0; j < 2; j++) {
        __half h0 = __float2half_rn(x[2 * j]);
        __half h1 = __float2half_rn(x[2 * j + 1]);
        __half l0 = __float2half_rn(x[2 * j] - __half2float(h0));
        __half l1 = __float2half_rn(x[2 * j + 1] - __half2float(h1));
        hp[j] = (uint32_t)__half_as_ushort(h0) |
                ((uint32_t)__half_as_ushort(h1) << 16);
        lp[j] = (uint32_t)__half_as_ushort(l0) |
                ((uint32_t)__half_as_ushort(l1) << 16);
    }
    *reinterpret_cast<uint2*>(reinterpret_cast<char*>(g_Ah) + i * 2) = make_uint2(hp[0], hp[1]);
    *reinterpret_cast<uint2*>(reinterpret_cast<char*>(g_Al) + i * 2) = make_uint2(lp[0], lp[1]);
}

struct WPtrs { const float* w[6]; };

__global__ void __launch_bounds__(256) split_wt(WPtrs wp)
{
    __shared__ float t[32][33];
    const int g = blockIdx.z;
    const float* __restrict__ W = wp.w[g];
    const int tx = threadIdx.x & 31, ty = threadIdx.x >> 5;
    const int n0 = blockIdx.x * 32, k0 = blockIdx.y * 32;
#pragma unroll
    for (int j = 0; j < 4; j++)
        t[ty + j * 8][tx] = W[(size_t)(k0 + ty + j * 8) * NDIM + n0 + tx];
    __syncthreads();
#pragma unroll
    for (int j = 0; j < 4; j++) {
        const float v = t[tx][ty + j * 8];
        const size_t o = (size_t)(g * 1024 + n0 + ty + j * 8) * KDIM + k0 + tx;
        g_Wh[o] = __float2half_rn(v);
    }
}

// ----------------------------------------------------------------------------
// gemm6: BM=BN=128, BK=32, 3 stages, 2 CTAs/SM, 2 products (Ahi*W + Alo*W)
// ----------------------------------------------------------------------------
#define SSTRIDE 40                      // fp16 elems per smem row (32 data + 8 pad)
#define MAT_ELEMS (128 * SSTRIDE)       // 5120
#define STAGE_ELEMS (3 * MAT_ELEMS)     // Ahi, Alo, W
#define NSTAGE 3
#define SMEM_BYTES (NSTAGE * STAGE_ELEMS * 2)   // 92160

__device__ __forceinline__ void cp16(uint32_t dst, const void* src)
{
    asm volatile("cp.async.cg.shared.global [%0], [%1], 16;"
                 :: "r"(dst), "l"(src) : "memory");
}
#define CP_COMMIT() asm volatile("cp.async.commit_group;" ::: "memory")
#define CP_WAIT(n)  asm volatile("cp.async.wait_group %0;" :: "n"(n) : "memory")

__device__ __forceinline__ void ldsm4(uint32_t* d, uint32_t addr)
{
    asm volatile("ldmatrix.sync.aligned.m8n8.x4.shared.b16 {%0,%1,%2,%3}, [%4];"
                 : "=r"(d[0]), "=r"(d[1]), "=r"(d[2]), "=r"(d[3]) : "r"(addr));
}

__device__ __forceinline__ void mma16816(float* c, const uint32_t* a,
                                         const uint32_t* b)
{
    asm volatile(
        "mma.sync.aligned.m16n8k16.row.col.f32.f16.f16.f32 "
        "{%0,%1,%2,%3}, {%4,%5,%6,%7}, {%8,%9}, {%0,%1,%2,%3};"
        : "+f"(c[0]), "+f"(c[1]), "+f"(c[2]), "+f"(c[3])
        : "r"(a[0]), "r"(a[1]), "r"(a[2]), "r"(a[3]), "r"(b[0]), "r"(b[1]));
}

__global__ void __launch_bounds__(256, 2) gemm6()
{
    extern __shared__ __half smem[];
    uint32_t sb;
    asm("{ .reg .u64 t; cvta.to.shared.u64 t, %1; cvt.u32.u64 %0, t; }"
        : "=r"(sb) : "l"(smem));

    const int tid  = threadIdx.x;
    const int lane = tid & 31, wid = tid >> 5;
    const int wm = wid >> 2, wn = wid & 3;          // 2 x 4 warps

    const int g  = blockIdx.z;
    const int bm = blockIdx.y * 128;
    const int bn = blockIdx.x * 128;
    const int arow = ((g & 1) << 12) + bm;
    const int wrow = (g << 10) + bn;

    const __half* gb[3] = {
        g_Ah + (size_t)arow * KDIM, g_Al + (size_t)arow * KDIM,
        g_Wh + (size_t)wrow * KDIM};

    // per-thread load mapping: 6 chunks of 16B (3 matrices x 512 chunks / 256 thr)
    int l_mat[6], l_row[6], l_ch[6];
#pragma unroll
    for (int i = 0; i < 6; i++) {
        const int idx = tid + i * 256;
        l_mat[i] = idx >> 9;                        // 0..2
        const int wi = idx & 511;
        l_row[i] = wi >> 2;
        l_ch[i]  = wi & 3;
    }

#define LOAD_STAGE(kt, s)                                                      \
    do {                                                                       \
        const uint32_t sbase_ = sb + (uint32_t)(s) * (STAGE_ELEMS * 2);        \
        _Pragma("unroll")                                                      \
        for (int i = 0; i < 6; i++) {                                          \
            const uint32_t dst = sbase_ +                                      \
                (uint32_t)(l_mat[i] * MAT_ELEMS + l_row[i] * SSTRIDE +         \
                           l_ch[i] * 8) * 2;                                   \
            cp16(dst, gb[l_mat[i]] + (size_t)l_row[i] * KDIM +                 \
                      (kt) * 32 + l_ch[i] * 8);                                \
        }                                                                      \
    } while (0)

    float acc[4][4][4];
#pragma unroll
    for (int mt = 0; mt < 4; mt++)
#pragma unroll
        for (int nt = 0; nt < 4; nt++)
#pragma unroll
            for (int j = 0; j < 4; j++) acc[mt][nt][j] = 0.f;

    LOAD_STAGE(0, 0); CP_COMMIT();
    LOAD_STAGE(1, 1); CP_COMMIT();
    LOAD_STAGE(2, 2); CP_COMMIT();

    const int a_r = (lane & 7) + ((lane >> 3) & 1) * 8;
    const int a_c = (lane >> 4) * 8;
    const int b_r = (lane & 7) + (lane >> 4) * 8;
    const int b_c = ((lane >> 3) & 1) * 8;

    for (int kt = 0; kt < 32; kt++) {
        CP_WAIT(2);                       // stage kt resident
        __syncthreads();

        const int slot = kt % 3;
        const uint32_t sbase = sb + (uint32_t)slot * (STAGE_ELEMS * 2);
#pragma unroll
        for (int ks = 0; ks < 2; ks++) {
            uint32_t a[4][4], bq[4][2];
            // W fragments (shared by both products)
#pragma unroll
            for (int p = 0; p < 2; p++) {
                uint32_t q[4];
                ldsm4(q, sbase + (uint32_t)(2 * MAT_ELEMS +
                        (wn * 32 + p * 16 + b_r) * SSTRIDE + ks * 16 + b_c) * 2);
                bq[2 * p][0] = q[0]; bq[2 * p][1] = q[1];
                bq[2 * p + 1][0] = q[2]; bq[2 * p + 1][1] = q[3];
            }
            // A_hi * W
#pragma unroll
            for (int mt = 0; mt < 4; mt++)
                ldsm4(a[mt], sbase +
                      (uint32_t)((wm * 64 + mt * 16 + a_r) * SSTRIDE +
                                 ks * 16 + a_c) * 2);
#pragma unroll
            for (int mt = 0; mt < 4; mt++)
#pragma unroll
                for (int nt = 0; nt < 4; nt++)
                    mma16816(acc[mt][nt], a[mt], bq[nt]);
            // A_lo * W (overwrite a[])
#pragma unroll
            for (int mt = 0; mt < 4; mt++)
                ldsm4(a[mt], sbase +
                      (uint32_t)(MAT_ELEMS +
                                 (wm * 64 + mt * 16 + a_r) * SSTRIDE +
                                 ks * 16 + a_c) * 2);
#pragma unroll
            for (int mt = 0; mt < 4; mt++)
#pragma unroll
                for (int nt = 0; nt < 4; nt++)
                    mma16816(acc[mt][nt], a[mt], bq[nt]);
        }

        __syncthreads();                  // everyone done reading stage kt
        if (kt + 3 < 32) LOAD_STAGE(kt + 3, slot);
        CP_COMMIT();
    }
    CP_WAIT(0);

    float* Cb = g_C + (size_t)g * GSZ;
    const int mrow = bm + wm * 64 + (lane >> 2);
    const int ncol = bn + wn * 32 + (lane & 3) * 2;
#pragma unroll
    for (int mt = 0; mt < 4; mt++) {
#pragma unroll
        for (int nt = 0; nt < 4; nt++) {
            float* p0 = Cb + (size_t)(mrow + mt * 16) * NDIM + ncol + nt * 8;
            *reinterpret_cast<float2*>(p0) =
                make_float2(acc[mt][nt][0], acc[mt][nt][1]);
            *reinterpret_cast<float2*>(p0 + 8 * NDIM) =
                make_float2(acc[mt][nt][2], acc[mt][nt][3]);
        }
    }
#undef LOAD_STAGE
}

// ----------------------------------------------------------------------------
// hyp_fused — 2-pass Gram (round-7 proven version: VPT=4, 256 thr)
// ----------------------------------------------------------------------------
#define RT 256
#define VPT 4

__device__ __forceinline__ float artanh_c(float x)
{
    x = fminf(fmaxf(x, -1.f + 1e-5f), 1.f - 1e-5f);
    return 0.5f * __logf(__fdividef(1.f + x, 1.f - x));
}

__device__ __forceinline__ float tanh_pos(float v)   // v >= 0
{
    return 1.f - __fdividef(2.f, __expf(2.f * v) + 1.f);
}

__device__ __forceinline__ float sigmoid_f(float v)
{
    return __fdividef(1.f, 1.f + __expf(-v));
}

__device__ __forceinline__ void safe_norm(float v2, float& inv_n, float& n)
{
    const float vc = fmaxf(v2, 1e-15f);
    inv_n = rsqrtf(vc);
    n = vc * inv_n;
}

__device__ __forceinline__ float mv_factor(float g2, float inv_xn, float atx)
{
    float inv_gn, gn;
    safe_norm(g2, inv_gn, gn);
    return tanh_pos(gn * inv_xn * atx) * inv_gn;
}

__device__ __forceinline__ void madd_coef(float ab, float a2, float b2,
                                          float& cA, float& cB)
{
    const float inv = __fdividef(1.f, 1.f + 2.f * ab + a2 * b2);
    cA = (1.f + 2.f * ab + b2) * inv;
    cB = (1.f - a2) * inv;
}

template <int N>
__device__ __forceinline__ void blockReduceN(float* v, float* buf)
{
    const int lane = threadIdx.x & 31, wid = threadIdx.x >> 5;
#pragma unroll
    for (int o = 16; o; o >>= 1)
#pragma unroll
        for (int i = 0; i < N; i++)
            v[i] += __shfl_xor_sync(0xffffffffu, v[i], o);
    if (lane == 0)
#pragma unroll
        for (int i = 0; i < N; i++) buf[wid * N + i] = v[i];
    __syncthreads();
#pragma unroll
    for (int i = 0; i < N; i++) {
        float s = 0.f;
#pragma unroll
        for (int w = 0; w < 8; w++) s += buf[w * N + i];
        v[i] = s;
    }
}

__global__ void __launch_bounds__(256) hyp_fused(
    const float* __restrict__ inp, const float* __restrict__ prevh,
    const float* __restrict__ bzp, const float* __restrict__ brp,
    const float* __restrict__ bhp, float* __restrict__ out)
{
    __shared__ float buf1[8 * 19];
    __shared__ float buf2[8 * 12];
    const int tid = threadIdx.x;
    const size_t off = (size_t)blockIdx.x * NDIM;

    float H[VPT], G0[VPT], G1[VPT], G2[VPT], G3[VPT], G4[VPT], G5[VPT];
    float BZ[VPT], BR[VPT], BH[VPT];
    float s[19];
#pragma unroll
    for (int i = 0; i < 19; i++) s[i] = 0.f;

#pragma unroll
    for (int j = 0; j < VPT; j++) {
        const int c = j * RT + tid;
        const float xv = inp[off + c];
        H[j]  = prevh[off + c];
        G0[j] = g_C[0 * GSZ + off + c];
        G1[j] = g_C[1 * GSZ + off + c];
        G2[j] = g_C[2 * GSZ + off + c];
        G3[j] = g_C[3 * GSZ + off + c];
        G4[j] = g_C[4 * GSZ + off + c];
        G5[j] = g_C[5 * GSZ + off + c];
        BZ[j] = bzp[c];
        BR[j] = brp[c];
        BH[j] = bhp[c];
        s[0]  = fmaf(xv, xv, s[0]);
        s[1]  = fmaf(H[j], H[j], s[1]);
        s[2]  = fmaf(G0[j], G0[j], s[2]);
        s[3]  = fmaf(G1[j], G1[j], s[3]);
        s[4]  = fmaf(G0[j], G1[j], s[4]);
        s[5]  = fmaf(G0[j], BZ[j], s[5]);
        s[6]  = fmaf(G1[j], BZ[j], s[6]);
        s[7]  = fmaf(BZ[j], BZ[j], s[7]);
        s[8]  = fmaf(G2[j], G2[j], s[8]);
        s[9]  = fmaf(G3[j], G3[j], s[9]);
        s[10] = fmaf(G2[j], G3[j], s[10]);
        s[11] = fmaf(G2[j], BR[j], s[11]);
        s[12] = fmaf(G3[j], BR[j], s[12]);
        s[13] = fmaf(BR[j], BR[j], s[13]);
        s[14] = fmaf(G5[j], G5[j], s[14]);
        s[15] = fmaf(G5[j], BH[j], s[15]);
        s[16] = fmaf(BH[j], BH[j], s[16]);
        s[17] = fmaf(G4[j], G4[j], s[17]);
        s[18] = fmaf(G4[j], H[j], s[18]);
    }
    blockReduceN<19>(s, buf1);
    const float xx = s[0], hh = s[1];
    const float g00 = s[2], g11 = s[3], g01 = s[4], g0z = s[5], g1z = s[6], zz = s[7];
    const float g22 = s[8], g33 = s[9], g23 = s[10], g2r = s[11], g3r = s[12], rrb = s[13];
    const float g55 = s[14], g5h = s[15], bhbh = s[16], g44 = s[17], g4H = s[18];

    float inv_xn, xn, inv_hn, hn;
    safe_norm(xx, inv_xn, xn);
    safe_norm(hh, inv_hn, hn);
    const float atx = artanh_c(xn);
    const float ath = artanh_c(hn);

    const float t0 = mv_factor(g00, inv_xn, atx);
    const float t1 = mv_factor(g11, inv_hn, ath);
    const float t2 = mv_factor(g22, inv_xn, atx);
    const float t3 = mv_factor(g33, inv_hn, ath);
    const float t4 = mv_factor(g44, inv_xn, atx);
    const float t5 = mv_factor(g55, inv_hn, ath);

    // z gate
    float cA, cB;
    madd_coef(t1 * g1z, t1 * t1 * g11, zz, cA, cB);
    const float u1 = cA * t1, u2 = cB;
    madd_coef(t0 * (u1 * g01 + u2 * g0z), t0 * t0 * g00,
              u1 * u1 * g11 + 2.f * u1 * u2 * g1z + u2 * u2 * zz, cA, cB);
    const float w0 = cA * t0, w1 = cB * u1, w2 = cB * u2;
    {
        const float nz2 = w0 * w0 * g00 + w1 * w1 * g11 + w2 * w2 * zz +
                          2.f * (w0 * w1 * g01 + w0 * w2 * g0z + w1 * w2 * g1z);
        float inv_nz, nz;
        safe_norm(nz2, inv_nz, nz);
        const float fz = artanh_c(nz) * inv_nz;
#pragma unroll
        for (int j = 0; j < VPT; j++)
            G0[j] = sigmoid_f(fz * (w0 * G0[j] + w1 * G1[j] + w2 * BZ[j]));
    }

    // r gate
    madd_coef(t3 * g3r, t3 * t3 * g33, rrb, cA, cB);
    const float v1 = cA * t3, v2 = cB;
    madd_coef(t2 * (v1 * g23 + v2 * g2r), t2 * t2 * g22,
              v1 * v1 * g33 + 2.f * v1 * v2 * g3r + v2 * v2 * rrb, cA, cB);
    const float y0 = cA * t2, y1 = cB * v1, y2 = cB * v2;
    {
        const float nr2 = y0 * y0 * g22 + y1 * y1 * g33 + y2 * y2 * rrb +
                          2.f * (y0 * y1 * g23 + y0 * y2 * g2r + y1 * y2 * g3r);
        float inv_nr, nr;
        safe_norm(nr2, inv_nr, nr);
        const float fr = artanh_c(nr) * inv_nr;
#pragma unroll
        for (int j = 0; j < VPT; j++)
            G1[j] = sigmoid_f(fr * (y0 * G2[j] + y1 * G3[j] + y2 * BR[j]));
    }

    // ahh = d5*G5 + db*BH
    madd_coef(t5 * g5h, t5 * t5 * g55, bhbh, cA, cB);
    const float d5 = cA * t5, db = cB;
    const float ahh2 = d5 * d5 * g55 + 2.f * d5 * db * g5h + db * db * bhbh;

    // pass-2 elementwise prep + sums
    float q[VPT];
    float s2[12];
#pragma unroll
    for (int i = 0; i < 12; i++) s2[i] = 0.f;
#pragma unroll
    for (int j = 0; j < VPT; j++) {
        q[j] = G1[j] * (d5 * G5[j] + db * BH[j]);
        const float z = G0[j];
        const float zh = z * H[j], zq = z * q[j], zg = z * G4[j];
        s2[0]  = fmaf(q[j], q[j], s2[0]);
        s2[1]  = fmaf(q[j], G4[j], s2[1]);
        s2[2]  = fmaf(q[j], H[j], s2[2]);
        s2[3]  = fmaf(zh, zh, s2[3]);
        s2[4]  = fmaf(zh, zq, s2[4]);
        s2[5]  = fmaf(zh, zg, s2[5]);
        s2[6]  = fmaf(zq, zq, s2[6]);
        s2[7]  = fmaf(zq, zg, s2[7]);
        s2[8]  = fmaf(zg, zg, s2[8]);
        s2[9]  = fmaf(H[j], zh, s2[9]);
        s2[10] = fmaf(H[j], zq, s2[10]);
        s2[11] = fmaf(H[j], zg, s2[11]);
    }
    blockReduceN<12>(s2, buf2);
    const float qq = s2[0], qg4 = s2[1], qh = s2[2];
    const float s11 = s2[3], s12 = s2[4], s13 = s2[5];
    const float s22 = s2[6], s23 = s2[7], s33 = s2[8];
    const float hzh = s2[9], hzq = s2[10], hzg4 = s2[11];

    float inv_na, na, inv_nq, nq;
    safe_norm(ahh2, inv_na, na);
    safe_norm(qq, inv_nq, nq);
    const float tp = tanh_pos(nq * inv_na * artanh_c(na)) * inv_nq;

    madd_coef(tp * t4 * qg4, tp * tp * qq, t4 * t4 * g44, cA, cB);
    const float bq = cA * tp, b4 = cB * t4;

    const float temp2 = bq * bq * qq + 2.f * bq * b4 * qg4 + b4 * b4 * g44;
    madd_coef(-(bq * qh + b4 * g4H), hh, temp2, cA, cB);
    const float alpha = -cA, bq2 = cB * bq, b42 = cB * b4;

    const float mh2 = alpha * alpha * hh + bq2 * bq2 * qq + b42 * b42 * g44 +
                      2.f * (alpha * bq2 * qh + alpha * b42 * g4H + bq2 * b42 * qg4);
    const float ux2 = alpha * alpha * s11 + bq2 * bq2 * s22 + b42 * b42 * s33 +
                      2.f * (alpha * bq2 * s12 + alpha * b42 * s13 + bq2 * b42 * s23);
    float inv_nmh, nmh, inv_nux, nux;
    safe_norm(mh2, inv_nmh, nmh);
    safe_norm(ux2, inv_nux, nux);
    const float tz = tanh_pos(nux * inv_nmh * artanh_c(nmh)) * inv_nux;

    madd_coef(tz * (alpha * hzh + bq2 * hzq + b42 * hzg4), hh, tz * tz * ux2,
              cA, cB);
    const float k0 = cA;
    const float kz = cB * tz;
    const float ka = kz * alpha, kb = kz * bq2, kc = kz * b42;

#pragma unroll
    for (int j = 0; j < VPT; j++) {
        const float z = G0[j];
        out[off + j * RT + tid] =
            k0 * H[j] + z * (ka * H[j] + kb * q[j] + kc * G4[j]);
    }
}

// ----------------------------------------------------------------------------
// launch
// ----------------------------------------------------------------------------
extern "C" void kernel_launch(void* const* d_in, const int* in_sizes, int n_in,
                              void* d_out, int out_size)
{
    const float* inp   = (const float*)d_in[0];
    const float* prevh = (const float*)d_in[1];
    WPtrs wp;
    wp.w[0] = (const float*)d_in[2];  // w_inp_z
    wp.w[1] = (const float*)d_in[3];  // w_hid_z
    wp.w[2] = (const float*)d_in[5];  // w_inp_r
    wp.w[3] = (const float*)d_in[6];  // w_hid_r
    wp.w[4] = (const float*)d_in[8];  // w_inp_h
    wp.w[5] = (const float*)d_in[9];  // w_hid_h
    const float* b_z = (const float*)d_in[4];
    const float* b_r = (const float*)d_in[7];
    const float* b_h = (const float*)d_in[10];
    float* out = (float*)d_out;

    cudaFuncSetAttribute(gemm6, cudaFuncAttributeMaxDynamicSharedMemorySize,
                         SMEM_BYTES);

    split_act<<<8192, 256>>>(inp, prevh);
    split_wt<<<dim3(32, 32, 6), 256>>>(wp);
    gemm6<<<dim3(8, 32, 6), 256, SMEM_BYTES>>>();
    hyp_fused<<<MDIM, 256>>>(inp, prevh, b_z, b_r, b_h, out);
}